// round 4
// baseline (speedup 1.0000x reference)
#include <cuda_runtime.h>

#define MAXN 100000
#define MAXE 1600000

// ---------------- scratch (device globals; no allocation allowed) ----------------
__device__ float d_h[MAXN * 64];      // node features buffer A
__device__ float d_h2[MAXN * 64];     // node features buffer B (double buffer)
__device__ float d_g[MAXN * 64];      // GAT-transformed features
__device__ float d_as[MAXN * 4];      // attention src logits per head (float4-aligned rows)
__device__ float d_ad[MAXN * 4];      // attention dst logits per head
__device__ float d_dinv[MAXN];
__device__ float d_Wc[3 * 64 * 64];   // fus_W_left @ e8_W, layout [layer][j][k]

// CSR: slots [0,N) = by-row (E8, neighbor=col), slots [N,2N) = by-col (GAT, neighbor=src)
__device__ int d_cnt[2 * MAXN];
__device__ int d_off[2 * MAXN];
__device__ int d_cur[2 * MAXN];
__device__ int d_bsum[1024];
__device__ int d_adj[2 * MAXE];

__device__ __forceinline__ float leaky02(float x) { return x > 0.f ? x : 0.2f * x; }

// ---------------- CSR build ----------------
__global__ void zero_cnt_kernel(int n2) {
    int i = blockIdx.x * blockDim.x + threadIdx.x;
    if (i < n2) d_cnt[i] = 0;
}

__global__ void count_kernel(const int* __restrict__ ei, int E, int n) {
    int e = blockIdx.x * blockDim.x + threadIdx.x;
    if (e < E) {
        atomicAdd(&d_cnt[ei[e]], 1);           // by row
        atomicAdd(&d_cnt[n + ei[E + e]], 1);   // by col
    }
}

__global__ void scan1_kernel(int n2) {
    __shared__ int s[256];
    int i = blockIdx.x * 256 + threadIdx.x;
    int v = (i < n2) ? d_cnt[i] : 0;
    s[threadIdx.x] = v;
    __syncthreads();
#pragma unroll
    for (int off = 1; off < 256; off <<= 1) {
        int x = (threadIdx.x >= off) ? s[threadIdx.x - off] : 0;
        __syncthreads();
        s[threadIdx.x] += x;
        __syncthreads();
    }
    if (i < n2) d_off[i] = s[threadIdx.x] - v;       // exclusive within block
    if (threadIdx.x == 255) d_bsum[blockIdx.x] = s[255];
}

__global__ void scan2_kernel(int nb) {   // single block, nb <= 1024
    __shared__ int s[1024];
    int v = (threadIdx.x < nb) ? d_bsum[threadIdx.x] : 0;
    s[threadIdx.x] = v;
    __syncthreads();
#pragma unroll
    for (int off = 1; off < 1024; off <<= 1) {
        int x = (threadIdx.x >= off) ? s[threadIdx.x - off] : 0;
        __syncthreads();
        s[threadIdx.x] += x;
        __syncthreads();
    }
    if (threadIdx.x < nb) d_bsum[threadIdx.x] = s[threadIdx.x] - v;  // exclusive
}

__global__ void scan3_kernel(int n2) {
    int i = blockIdx.x * blockDim.x + threadIdx.x;
    if (i < n2) {
        int o = d_off[i] + d_bsum[i >> 8];
        d_off[i] = o;
        d_cur[i] = o;
    }
}

__global__ void fill_kernel(const int* __restrict__ ei, int E, int n) {
    int e = blockIdx.x * blockDim.x + threadIdx.x;
    if (e < E) {
        int r = ei[e], c = ei[E + e];
        int p = atomicAdd(&d_cur[r], 1);
        d_adj[p] = c;                   // E8: neighbors (cols) of row r
        int p2 = atomicAdd(&d_cur[n + c], 1);
        d_adj[p2] = r;                  // GAT: in-neighbors (srcs) of dst c
    }
}

__global__ void dinv_kernel(int n) {
    int i = blockIdx.x * blockDim.x + threadIdx.x;
    if (i < n) {
        float dg = (float)d_cnt[n + i];       // degree by col
        d_dinv[i] = dg > 0.f ? rsqrtf(dg) : 0.f;
    }
}

// ---------------- Wc = fus_W[:, :64] @ e8_W (per layer) ----------------
__global__ void wc_kernel(const float* __restrict__ fusW, const float* __restrict__ e8W) {
    int layer = blockIdx.x;
    int idx = blockIdx.y * 256 + threadIdx.x;
    int j = idx >> 6, k = idx & 63;
    const float* F = fusW + layer * 64 * 128;
    const float* Ew = e8W + layer * 64 * 64;
    float acc = 0.f;
#pragma unroll
    for (int m = 0; m < 64; m++) acc += F[j * 128 + m] * Ew[m * 64 + k];
    d_Wc[layer * 4096 + j * 64 + k] = acc;
}

// ---------------- embedding: h = x @ emb_W^T + b (into d_h) ----------------
__global__ void emb_kernel(const float* __restrict__ x, const float* __restrict__ W,
                           const float* __restrict__ b, int n) {
    __shared__ float Ws[64 * 65];
    __shared__ float bs[64];
    for (int idx = threadIdx.x; idx < 4096; idx += blockDim.x) {
        int j = idx >> 6, k = idx & 63;
        Ws[j * 65 + k] = W[idx];
    }
    if (threadIdx.x < 64) bs[threadIdx.x] = b[threadIdx.x];
    __syncthreads();
    int warp = threadIdx.x >> 5, t = threadIdx.x & 31;
    for (int node = blockIdx.x * 8 + warp; node < n; node += gridDim.x * 8) {
        float in0 = x[node * 64 + t];
        float in1 = x[node * 64 + t + 32];
        float acc0 = bs[t], acc1 = bs[t + 32];
#pragma unroll
        for (int k = 0; k < 32; k++) {
            float xk = __shfl_sync(0xffffffffu, in0, k);
            acc0 += xk * Ws[t * 65 + k];
            acc1 += xk * Ws[(t + 32) * 65 + k];
        }
#pragma unroll
        for (int k = 0; k < 32; k++) {
            float xk = __shfl_sync(0xffffffffu, in1, k);
            acc0 += xk * Ws[t * 65 + 32 + k];
            acc1 += xk * Ws[(t + 32) * 65 + 32 + k];
        }
        d_h[node * 64 + t] = acc0;
        d_h[node * 64 + t + 32] = acc1;
    }
}

// ---------------- N1: g = hin @ gat_W, attention logits ----------------
__global__ void n1_kernel(const float* __restrict__ gatW, const float* __restrict__ attS,
                          const float* __restrict__ attD, int layer, int flip, int n) {
    const float* hin = flip ? d_h2 : d_h;
    __shared__ float Ws[64 * 65];   // Ws[j*65+k] = gat_W[k][j]
    const float* W = gatW + layer * 4096;
    for (int idx = threadIdx.x; idx < 4096; idx += blockDim.x) {
        int k = idx >> 6, j = idx & 63;
        Ws[j * 65 + k] = W[idx];
    }
    __syncthreads();
    int warp = threadIdx.x >> 5, t = threadIdx.x & 31;
    float as0 = attS[layer * 64 + t], as1 = attS[layer * 64 + t + 32];
    float ad0 = attD[layer * 64 + t], ad1 = attD[layer * 64 + t + 32];
    for (int node = blockIdx.x * 8 + warp; node < n; node += gridDim.x * 8) {
        float in0 = hin[node * 64 + t], in1 = hin[node * 64 + t + 32];
        float g0 = 0.f, g1 = 0.f;
#pragma unroll
        for (int k = 0; k < 32; k++) {
            float xk = __shfl_sync(0xffffffffu, in0, k);
            g0 += xk * Ws[t * 65 + k];
            g1 += xk * Ws[(t + 32) * 65 + k];
        }
#pragma unroll
        for (int k = 0; k < 32; k++) {
            float xk = __shfl_sync(0xffffffffu, in1, k);
            g0 += xk * Ws[t * 65 + 32 + k];
            g1 += xk * Ws[(t + 32) * 65 + 32 + k];
        }
        d_g[node * 64 + t] = g0;
        d_g[node * 64 + t + 32] = g1;

        float ps0 = g0 * as0, ps1 = g1 * as1;
        float pd0 = g0 * ad0, pd1 = g1 * ad1;
#pragma unroll
        for (int off = 8; off; off >>= 1) {
            ps0 += __shfl_xor_sync(0xffffffffu, ps0, off);
            ps1 += __shfl_xor_sync(0xffffffffu, ps1, off);
            pd0 += __shfl_xor_sync(0xffffffffu, pd0, off);
            pd1 += __shfl_xor_sync(0xffffffffu, pd1, off);
        }
        if ((t & 15) == 0) {
            int hh = t >> 4;
            d_as[node * 4 + hh] = ps0;
            d_as[node * 4 + 2 + hh] = ps1;
            d_ad[node * 4 + hh] = pd0;
            d_ad[node * 4 + 2 + hh] = pd1;
        }
    }
}

// ---------------- fused: CSR gather (E8 + GAT) + GEMVs + residual + LN + ReLU ----------------
// reads hin, writes hout (double-buffered). Chunk-of-32 index staging + shfl broadcast.
__global__ void __launch_bounds__(256) layer_kernel(
        const float* __restrict__ fusW, const float* __restrict__ fusB,
        const float* __restrict__ gatB, const float* __restrict__ lnG,
        const float* __restrict__ lnB, int layer, int flip, int n) {
    const float* hin = flip ? d_h2 : d_h;
    float* hout = flip ? d_h : d_h2;
    __shared__ float W1s[64 * 65];  // Wc[layer] acting on agg
    __shared__ float W2s[64 * 65];  // fus_W right half acting on x_gat
    __shared__ float fb[64], gb[64], lg[64], lb[64];
    const float* Wc = d_Wc + layer * 4096;
    const float* F = fusW + layer * 64 * 128;
    for (int idx = threadIdx.x; idx < 4096; idx += blockDim.x) {
        int j = idx >> 6, k = idx & 63;
        W1s[j * 65 + k] = Wc[idx];
        W2s[j * 65 + k] = F[j * 128 + 64 + k];
    }
    if (threadIdx.x < 64) {
        fb[threadIdx.x] = fusB[layer * 64 + threadIdx.x];
        gb[threadIdx.x] = gatB[layer * 64 + threadIdx.x];
        lg[threadIdx.x] = lnG[layer * 64 + threadIdx.x];
        lb[threadIdx.x] = lnB[layer * 64 + threadIdx.x];
    }
    __syncthreads();
    int warp = threadIdx.x >> 5, t = threadIdx.x & 31;
    int hA = t >> 4;   // 0 or 1; head for column t is hA, for t+32 is hA+2

    for (int node = blockIdx.x * 8 + warp; node < n; node += gridDim.x * 8) {
        // ---------- GAT gather over in-neighbors (col-CSR) ----------
        float4 adv = *reinterpret_cast<const float4*>(&d_ad[node * 4]);  // all 4 heads of dst
        float4 asn = *reinterpret_cast<const float4*>(&d_as[node * 4]);
        // self-loop
        float eeS0, eeS1;
        {
            float e0 = __expf(leaky02(asn.x + adv.x));
            float e1 = __expf(leaky02(asn.y + adv.y));
            float e2 = __expf(leaky02(asn.z + adv.z));
            float e3 = __expf(leaky02(asn.w + adv.w));
            eeS0 = hA ? e1 : e0;
            eeS1 = hA ? e3 : e2;
        }
        float w0 = eeS0 * d_g[node * 64 + t];
        float w1 = eeS1 * d_g[node * 64 + t + 32];
        float s0 = eeS0, s1 = eeS1;
        {
            int beg = d_off[n + node];
            int dc = d_cnt[n + node];
            for (int base = 0; base < dc; base += 32) {
                int rem = dc - base;
                int m = rem < 32 ? rem : 32;
                int idx = d_adj[beg + base + (t < rem ? t : 0)];
                // lane-local: all 4 head exponentials for its neighbor
                float4 asv = *reinterpret_cast<const float4*>(&d_as[idx * 4]);
                float e0 = __expf(leaky02(asv.x + adv.x));
                float e1 = __expf(leaky02(asv.y + adv.y));
                float e2 = __expf(leaky02(asv.z + adv.z));
                float e3 = __expf(leaky02(asv.w + adv.w));
#pragma unroll 8
                for (int j = 0; j < m; j++) {
                    int src = __shfl_sync(0xffffffffu, idx, j);
                    float f0 = __shfl_sync(0xffffffffu, e0, j);
                    float f1 = __shfl_sync(0xffffffffu, e1, j);
                    float f2 = __shfl_sync(0xffffffffu, e2, j);
                    float f3 = __shfl_sync(0xffffffffu, e3, j);
                    float eA = hA ? f1 : f0;
                    float eB = hA ? f3 : f2;
                    w0 += eA * d_g[src * 64 + t];
                    w1 += eB * d_g[src * 64 + t + 32];
                    s0 += eA;
                    s1 += eB;
                }
            }
        }
        float x0 = w0 / s0 + gb[t];
        float x1 = w1 / s1 + gb[t + 32];

        // ---------- E8 gather over row neighbors (row-CSR), immutable hin ----------
        float a0 = 0.f, a1 = 0.f;
        {
            int beg = d_off[node];
            int dr = d_cnt[node];
            for (int base = 0; base < dr; base += 32) {
                int rem = dr - base;
                int m = rem < 32 ? rem : 32;
                int idx = d_adj[beg + base + (t < rem ? t : 0)];
                float dv = d_dinv[idx];
#pragma unroll 8
                for (int j = 0; j < m; j++) {
                    int c = __shfl_sync(0xffffffffu, idx, j);
                    float dvj = __shfl_sync(0xffffffffu, dv, j);
                    a0 += dvj * hin[c * 64 + t];
                    a1 += dvj * hin[c * 64 + t + 32];
                }
            }
            float dvr = d_dinv[node];
            a0 *= dvr;
            a1 *= dvr;
        }

        // ---------- GEMVs: Wc@agg + fus_right@x_gat ----------
        float acc0 = fb[t], acc1 = fb[t + 32];
#pragma unroll
        for (int k = 0; k < 32; k++) {
            float ak = __shfl_sync(0xffffffffu, a0, k);
            acc0 += ak * W1s[t * 65 + k];
            acc1 += ak * W1s[(t + 32) * 65 + k];
        }
#pragma unroll
        for (int k = 0; k < 32; k++) {
            float ak = __shfl_sync(0xffffffffu, a1, k);
            acc0 += ak * W1s[t * 65 + 32 + k];
            acc1 += ak * W1s[(t + 32) * 65 + 32 + k];
        }
#pragma unroll
        for (int k = 0; k < 32; k++) {
            float xk = __shfl_sync(0xffffffffu, x0, k);
            acc0 += xk * W2s[t * 65 + k];
            acc1 += xk * W2s[(t + 32) * 65 + k];
        }
#pragma unroll
        for (int k = 0; k < 32; k++) {
            float xk = __shfl_sync(0xffffffffu, x1, k);
            acc0 += xk * W2s[t * 65 + 32 + k];
            acc1 += xk * W2s[(t + 32) * 65 + 32 + k];
        }
        // residual
        acc0 += hin[node * 64 + t];
        acc1 += hin[node * 64 + t + 32];
        // LayerNorm + ReLU
        float ssum = acc0 + acc1;
#pragma unroll
        for (int off = 16; off; off >>= 1) ssum += __shfl_xor_sync(0xffffffffu, ssum, off);
        float mu = ssum * (1.f / 64.f);
        float dd0 = acc0 - mu, dd1 = acc1 - mu;
        float vs = dd0 * dd0 + dd1 * dd1;
#pragma unroll
        for (int off = 16; off; off >>= 1) vs += __shfl_xor_sync(0xffffffffu, vs, off);
        float rstd = rsqrtf(vs * (1.f / 64.f) + 1e-5f);
        float o0 = fmaxf(dd0 * rstd * lg[t] + lb[t], 0.f);
        float o1 = fmaxf(dd1 * rstd * lg[t + 32] + lb[t + 32], 0.f);
        hout[node * 64 + t] = o0;
        hout[node * 64 + t + 32] = o1;
    }
}

// ---------------- readout (reads d_h2: output buffer after 3 layers) ----------------
__global__ void readout_kernel(const float* __restrict__ rW1, const float* __restrict__ rb1,
                               const float* __restrict__ rW2, const float* __restrict__ rb2,
                               float* __restrict__ out, int n) {
    const float* hin = d_h2;
    __shared__ float W1s[32 * 65];
    __shared__ float b1s[32], W2s[32];
    for (int idx = threadIdx.x; idx < 2048; idx += blockDim.x) {
        int m = idx >> 6, k = idx & 63;
        W1s[m * 65 + k] = rW1[idx];
    }
    if (threadIdx.x < 32) {
        b1s[threadIdx.x] = rb1[threadIdx.x];
        W2s[threadIdx.x] = rW2[threadIdx.x];
    }
    __syncthreads();
    float b2 = rb2[0];
    int warp = threadIdx.x >> 5, t = threadIdx.x & 31;
    for (int node = blockIdx.x * 8 + warp; node < n; node += gridDim.x * 8) {
        float in0 = hin[node * 64 + t], in1 = hin[node * 64 + t + 32];
        float acc = b1s[t];
#pragma unroll
        for (int k = 0; k < 32; k++) {
            float xk = __shfl_sync(0xffffffffu, in0, k);
            acc += xk * W1s[t * 65 + k];
        }
#pragma unroll
        for (int k = 0; k < 32; k++) {
            float xk = __shfl_sync(0xffffffffu, in1, k);
            acc += xk * W1s[t * 65 + 32 + k];
        }
        acc = fmaxf(acc, 0.f);
        float p = acc * W2s[t];
#pragma unroll
        for (int off = 16; off; off >>= 1) p += __shfl_xor_sync(0xffffffffu, p, off);
        if (t == 0) out[node] = 1.f / (1.f + __expf(-(p + b2)));
    }
}

// ---------------- launch ----------------
extern "C" void kernel_launch(void* const* d_in, const int* in_sizes, int n_in,
                              void* d_out, int out_size) {
    const float* x    = (const float*)d_in[0];
    const int*   ei   = (const int*)d_in[1];
    const float* embW = (const float*)d_in[2];
    const float* embB = (const float*)d_in[3];
    const float* e8W  = (const float*)d_in[4];
    const float* gatW = (const float*)d_in[5];
    const float* attS = (const float*)d_in[6];
    const float* attD = (const float*)d_in[7];
    const float* gatB = (const float*)d_in[8];
    const float* fusW = (const float*)d_in[9];
    const float* fusB = (const float*)d_in[10];
    const float* lnG  = (const float*)d_in[11];
    const float* lnB  = (const float*)d_in[12];
    const float* rW1  = (const float*)d_in[13];
    const float* rb1  = (const float*)d_in[14];
    const float* rW2  = (const float*)d_in[15];
    const float* rb2  = (const float*)d_in[16];
    float* out = (float*)d_out;

    int n = in_sizes[0] / 64;
    int E = in_sizes[1] / 2;
    int n2 = 2 * n;
    int nb = (n2 + 255) / 256;

    // CSR build (graph is constant across the 3 layers)
    zero_cnt_kernel<<<(n2 + 255) / 256, 256>>>(n2);
    count_kernel<<<(E + 255) / 256, 256>>>(ei, E, n);
    scan1_kernel<<<nb, 256>>>(n2);
    scan2_kernel<<<1, 1024>>>(nb);
    scan3_kernel<<<(n2 + 255) / 256, 256>>>(n2);
    fill_kernel<<<(E + 255) / 256, 256>>>(ei, E, n);
    dinv_kernel<<<(n + 255) / 256, 256>>>(n);

    dim3 wcg(3, 16);
    wc_kernel<<<wcg, 256>>>(fusW, e8W);

    int ngrid = 1563;
    emb_kernel<<<ngrid, 256>>>(x, embW, embB, n);

    // flip: layer l reads buffer (l%2) [0 -> d_h, 1 -> d_h2], writes the other.
    for (int l = 0; l < 3; l++) {
        int flip = l & 1;
        n1_kernel<<<ngrid, 256>>>(gatW, attS, attD, l, flip, n);
        layer_kernel<<<ngrid, 256>>>(fusW, fusB, gatB, lnG, lnB, l, flip, n);
    }
    // layer 2: flip=0 -> writes d_h2
    readout_kernel<<<ngrid, 256>>>(rW1, rb1, rW2, rb2, out, n);
}

// round 5
// speedup vs baseline: 1.0233x; 1.0233x over previous
#include <cuda_runtime.h>

#define MAXN 100000
#define MAXE 1600000

// ---------------- scratch (device globals; no allocation allowed) ----------------
__device__ float d_h[MAXN * 64];      // node features buffer A
__device__ float d_h2[MAXN * 64];     // node features buffer B (double buffer)
__device__ float d_g[MAXN * 64];      // GAT-transformed features
__device__ float d_as[MAXN * 4];      // attention src logits per head
__device__ float d_ad[MAXN * 4];      // attention dst logits per head
__device__ float d_dinv[MAXN];
__device__ float d_Wc[3 * 64 * 64];   // fus_W_left @ e8_W, layout [layer][j][k]

// CSR: slots [0,N) = by-row (E8, neighbor=col), slots [N,2N) = by-col (GAT, neighbor=src)
__device__ int d_cnt[2 * MAXN];
__device__ int d_off[2 * MAXN];
__device__ int d_cur[2 * MAXN];
__device__ int d_total;
__device__ int d_adj[2 * MAXE];

__device__ __forceinline__ float leaky02(float x) { return x > 0.f ? x : 0.2f * x; }

// ---------------- CSR build ----------------
__global__ void zero_cnt_kernel(int n2) {
    int i = blockIdx.x * blockDim.x + threadIdx.x;
    if (i < n2) d_cnt[i] = 0;
    if (i == 0) d_total = 0;
}

__global__ void count_kernel(const int* __restrict__ ei, int E, int n) {
    int e = blockIdx.x * blockDim.x + threadIdx.x;
    if (e < E) {
        atomicAdd(&d_cnt[ei[e]], 1);           // by row
        atomicAdd(&d_cnt[n + ei[E + e]], 1);   // by col
    }
}

__global__ void alloc_kernel(int n2) {
    int i = blockIdx.x * blockDim.x + threadIdx.x;
    if (i < n2) {
        int c = d_cnt[i];
        int o = atomicAdd(&d_total, c);
        d_off[i] = o;
        d_cur[i] = o;
    }
}

__global__ void fill_kernel(const int* __restrict__ ei, int E, int n) {
    int e = blockIdx.x * blockDim.x + threadIdx.x;
    if (e < E) {
        int r = ei[e], c = ei[E + e];
        int p = atomicAdd(&d_cur[r], 1);
        d_adj[p] = c;                   // E8: neighbors (cols) of row r
        int p2 = atomicAdd(&d_cur[n + c], 1);
        d_adj[p2] = r;                  // GAT: in-neighbors (srcs) of dst c
    }
}

// ---------------- nodeprep: dinv + emb + n1(layer0) + Wc ----------------
// blocks [0, ngrid): per-node work.  blocks [ngrid, ngrid+48): Wc precompute.
__global__ void __launch_bounds__(256) nodeprep_kernel(
        const float* __restrict__ x, const float* __restrict__ embW,
        const float* __restrict__ embB, const float* __restrict__ gatW,
        const float* __restrict__ attS, const float* __restrict__ attD,
        const float* __restrict__ fusW, const float* __restrict__ e8W,
        int ngrid, int n) {
    if (blockIdx.x >= (unsigned)ngrid) {
        // ---- Wc = fus_W[:, :64] @ e8_W ----
        int bid = blockIdx.x - ngrid;            // 0..47
        int gidx = bid * 256 + threadIdx.x;      // 0..12287
        if (gidx < 3 * 4096) {
            int layer = gidx >> 12;
            int idx = gidx & 4095;
            int j = idx >> 6, k = idx & 63;
            const float* F = fusW + layer * 64 * 128;
            const float* Ew = e8W + layer * 64 * 64;
            float acc = 0.f;
#pragma unroll
            for (int m = 0; m < 64; m++) acc += F[j * 128 + m] * Ew[m * 64 + k];
            d_Wc[layer * 4096 + j * 64 + k] = acc;
        }
        return;
    }
    __shared__ float We[64 * 65];   // emb: We[j*65+k] = embW[j][k]
    __shared__ float Wg[64 * 65];   // gat: Wg[j*65+k] = gatW[k][j]  (layer 0)
    __shared__ float bs[64];
    for (int idx = threadIdx.x; idx < 4096; idx += blockDim.x) {
        int j = idx >> 6, k = idx & 63;
        We[j * 65 + k] = embW[idx];
        Wg[k * 65 + j] = gatW[idx];   // gatW row j (input dim), col k (output) -> Wg[out][in]
    }
    if (threadIdx.x < 64) bs[threadIdx.x] = embB[threadIdx.x];
    __syncthreads();
    int warp = threadIdx.x >> 5, t = threadIdx.x & 31;
    float as0 = attS[t], as1 = attS[t + 32];
    float ad0 = attD[t], ad1 = attD[t + 32];
    for (int node = blockIdx.x * 8 + warp; node < n; node += ngrid * 8) {
        // dinv
        if (t == 0) {
            float dg = (float)d_cnt[n + node];
            d_dinv[node] = dg > 0.f ? rsqrtf(dg) : 0.f;
        }
        // ---- emb ----
        float in0 = x[node * 64 + t];
        float in1 = x[node * 64 + t + 32];
        float h0 = bs[t], h1 = bs[t + 32];
#pragma unroll
        for (int k = 0; k < 32; k++) {
            float xk = __shfl_sync(0xffffffffu, in0, k);
            h0 += xk * We[t * 65 + k];
            h1 += xk * We[(t + 32) * 65 + k];
        }
#pragma unroll
        for (int k = 0; k < 32; k++) {
            float xk = __shfl_sync(0xffffffffu, in1, k);
            h0 += xk * We[t * 65 + 32 + k];
            h1 += xk * We[(t + 32) * 65 + 32 + k];
        }
        d_h[node * 64 + t] = h0;
        d_h[node * 64 + t + 32] = h1;
        // ---- n1 (layer 0): g = h @ gatW, from register h ----
        float g0 = 0.f, g1 = 0.f;
#pragma unroll
        for (int k = 0; k < 32; k++) {
            float xk = __shfl_sync(0xffffffffu, h0, k);
            g0 += xk * Wg[t * 65 + k];
            g1 += xk * Wg[(t + 32) * 65 + k];
        }
#pragma unroll
        for (int k = 0; k < 32; k++) {
            float xk = __shfl_sync(0xffffffffu, h1, k);
            g0 += xk * Wg[t * 65 + 32 + k];
            g1 += xk * Wg[(t + 32) * 65 + 32 + k];
        }
        d_g[node * 64 + t] = g0;
        d_g[node * 64 + t + 32] = g1;
        float ps0 = g0 * as0, ps1 = g1 * as1;
        float pd0 = g0 * ad0, pd1 = g1 * ad1;
#pragma unroll
        for (int off = 8; off; off >>= 1) {
            ps0 += __shfl_xor_sync(0xffffffffu, ps0, off);
            ps1 += __shfl_xor_sync(0xffffffffu, ps1, off);
            pd0 += __shfl_xor_sync(0xffffffffu, pd0, off);
            pd1 += __shfl_xor_sync(0xffffffffu, pd1, off);
        }
        if ((t & 15) == 0) {
            int hh = t >> 4;
            d_as[node * 4 + hh] = ps0;
            d_as[node * 4 + 2 + hh] = ps1;
            d_ad[node * 4 + hh] = pd0;
            d_ad[node * 4 + 2 + hh] = pd1;
        }
    }
}

// ---------------- N1 (layers 1,2): g = hin @ gat_W, attention logits ----------------
__global__ void __launch_bounds__(256) n1_kernel(
        const float* __restrict__ gatW, const float* __restrict__ attS,
        const float* __restrict__ attD, int layer, int flip, int n) {
    const float* hin = flip ? d_h2 : d_h;
    __shared__ float Ws[64 * 65];   // Ws[j*65+k] = gat_W[k][j]
    const float* W = gatW + layer * 4096;
    for (int idx = threadIdx.x; idx < 4096; idx += blockDim.x) {
        int k = idx >> 6, j = idx & 63;
        Ws[j * 65 + k] = W[idx];
    }
    __syncthreads();
    int warp = threadIdx.x >> 5, t = threadIdx.x & 31;
    float as0 = attS[layer * 64 + t], as1 = attS[layer * 64 + t + 32];
    float ad0 = attD[layer * 64 + t], ad1 = attD[layer * 64 + t + 32];
    for (int node = blockIdx.x * 8 + warp; node < n; node += gridDim.x * 8) {
        float in0 = hin[node * 64 + t], in1 = hin[node * 64 + t + 32];
        float g0 = 0.f, g1 = 0.f;
#pragma unroll
        for (int k = 0; k < 32; k++) {
            float xk = __shfl_sync(0xffffffffu, in0, k);
            g0 += xk * Ws[t * 65 + k];
            g1 += xk * Ws[(t + 32) * 65 + k];
        }
#pragma unroll
        for (int k = 0; k < 32; k++) {
            float xk = __shfl_sync(0xffffffffu, in1, k);
            g0 += xk * Ws[t * 65 + 32 + k];
            g1 += xk * Ws[(t + 32) * 65 + 32 + k];
        }
        d_g[node * 64 + t] = g0;
        d_g[node * 64 + t + 32] = g1;

        float ps0 = g0 * as0, ps1 = g1 * as1;
        float pd0 = g0 * ad0, pd1 = g1 * ad1;
#pragma unroll
        for (int off = 8; off; off >>= 1) {
            ps0 += __shfl_xor_sync(0xffffffffu, ps0, off);
            ps1 += __shfl_xor_sync(0xffffffffu, ps1, off);
            pd0 += __shfl_xor_sync(0xffffffffu, pd0, off);
            pd1 += __shfl_xor_sync(0xffffffffu, pd1, off);
        }
        if ((t & 15) == 0) {
            int hh = t >> 4;
            d_as[node * 4 + hh] = ps0;
            d_as[node * 4 + 2 + hh] = ps1;
            d_ad[node * 4 + hh] = pd0;
            d_ad[node * 4 + 2 + hh] = pd1;
        }
    }
}

// ---------------- fused: CSR gather (E8 + GAT) + GEMVs + residual + LN + ReLU ----------------
__global__ void __launch_bounds__(256) layer_kernel(
        const float* __restrict__ fusW, const float* __restrict__ fusB,
        const float* __restrict__ gatB, const float* __restrict__ lnG,
        const float* __restrict__ lnB, int layer, int flip, int n) {
    const float* hin = flip ? d_h2 : d_h;
    float* hout = flip ? d_h : d_h2;
    __shared__ float W1s[64 * 65];  // Wc[layer] acting on agg
    __shared__ float W2s[64 * 65];  // fus_W right half acting on x_gat
    __shared__ float fb[64], gb[64], lg[64], lb[64];
    const float* Wc = d_Wc + layer * 4096;
    const float* F = fusW + layer * 64 * 128;
    for (int idx = threadIdx.x; idx < 4096; idx += blockDim.x) {
        int j = idx >> 6, k = idx & 63;
        W1s[j * 65 + k] = Wc[idx];
        W2s[j * 65 + k] = F[j * 128 + 64 + k];
    }
    if (threadIdx.x < 64) {
        fb[threadIdx.x] = fusB[layer * 64 + threadIdx.x];
        gb[threadIdx.x] = gatB[layer * 64 + threadIdx.x];
        lg[threadIdx.x] = lnG[layer * 64 + threadIdx.x];
        lb[threadIdx.x] = lnB[layer * 64 + threadIdx.x];
    }
    __syncthreads();
    int warp = threadIdx.x >> 5, t = threadIdx.x & 31;
    int hA = t >> 4, hB = 2 + (t >> 4);

    for (int node = blockIdx.x * 8 + warp; node < n; node += gridDim.x * 8) {
        // --- GAT: self-loop init + gather over in-neighbors (col-CSR) ---
        float adA = d_ad[node * 4 + hA];
        float adB = d_ad[node * 4 + hB];
        float eeS0 = __expf(leaky02(d_as[node * 4 + hA] + adA));
        float eeS1 = __expf(leaky02(d_as[node * 4 + hB] + adB));
        float w0 = eeS0 * d_g[node * 64 + t];
        float w1 = eeS1 * d_g[node * 64 + t + 32];
        float s0 = eeS0, s1 = eeS1;
        {
            int beg = d_off[n + node];
            int dc = d_cnt[n + node];
            for (int i = 0; i < dc; i++) {
                int src = __ldg(&d_adj[beg + i]);
                float g0 = d_g[src * 64 + t];
                float g1 = d_g[src * 64 + t + 32];
                float ee0 = __expf(leaky02(d_as[src * 4 + hA] + adA));
                float ee1 = __expf(leaky02(d_as[src * 4 + hB] + adB));
                w0 += ee0 * g0;
                w1 += ee1 * g1;
                s0 += ee0;
                s1 += ee1;
            }
        }
        float x0 = w0 / s0 + gb[t];
        float x1 = w1 / s1 + gb[t + 32];

        // --- E8: gather over row neighbors (row-CSR), immutable hin ---
        float a0 = 0.f, a1 = 0.f;
        {
            int beg = d_off[node];
            int dr = d_cnt[node];
            for (int i = 0; i < dr; i++) {
                int c = __ldg(&d_adj[beg + i]);
                float dv = d_dinv[c];
                a0 += dv * hin[c * 64 + t];
                a1 += dv * hin[c * 64 + t + 32];
            }
            float dvr = d_dinv[node];
            a0 *= dvr;
            a1 *= dvr;
        }

        // --- GEMVs: Wc@agg + fus_right@x_gat ---
        float acc0 = fb[t], acc1 = fb[t + 32];
#pragma unroll
        for (int k = 0; k < 32; k++) {
            float ak = __shfl_sync(0xffffffffu, a0, k);
            acc0 += ak * W1s[t * 65 + k];
            acc1 += ak * W1s[(t + 32) * 65 + k];
        }
#pragma unroll
        for (int k = 0; k < 32; k++) {
            float ak = __shfl_sync(0xffffffffu, a1, k);
            acc0 += ak * W1s[t * 65 + 32 + k];
            acc1 += ak * W1s[(t + 32) * 65 + 32 + k];
        }
#pragma unroll
        for (int k = 0; k < 32; k++) {
            float xk = __shfl_sync(0xffffffffu, x0, k);
            acc0 += xk * W2s[t * 65 + k];
            acc1 += xk * W2s[(t + 32) * 65 + k];
        }
#pragma unroll
        for (int k = 0; k < 32; k++) {
            float xk = __shfl_sync(0xffffffffu, x1, k);
            acc0 += xk * W2s[t * 65 + 32 + k];
            acc1 += xk * W2s[(t + 32) * 65 + 32 + k];
        }
        // residual
        acc0 += hin[node * 64 + t];
        acc1 += hin[node * 64 + t + 32];
        // LayerNorm + ReLU
        float ssum = acc0 + acc1;
#pragma unroll
        for (int off = 16; off; off >>= 1) ssum += __shfl_xor_sync(0xffffffffu, ssum, off);
        float mu = ssum * (1.f / 64.f);
        float dd0 = acc0 - mu, dd1 = acc1 - mu;
        float vs = dd0 * dd0 + dd1 * dd1;
#pragma unroll
        for (int off = 16; off; off >>= 1) vs += __shfl_xor_sync(0xffffffffu, vs, off);
        float rstd = rsqrtf(vs * (1.f / 64.f) + 1e-5f);
        float o0 = fmaxf(dd0 * rstd * lg[t] + lb[t], 0.f);
        float o1 = fmaxf(dd1 * rstd * lg[t + 32] + lb[t + 32], 0.f);
        hout[node * 64 + t] = o0;
        hout[node * 64 + t + 32] = o1;
    }
}

// ---------------- readout (reads d_h2: output buffer after 3 layers) ----------------
__global__ void readout_kernel(const float* __restrict__ rW1, const float* __restrict__ rb1,
                               const float* __restrict__ rW2, const float* __restrict__ rb2,
                               float* __restrict__ out, int n) {
    const float* hin = d_h2;
    __shared__ float W1s[32 * 65];
    __shared__ float b1s[32], W2s[32];
    for (int idx = threadIdx.x; idx < 2048; idx += blockDim.x) {
        int m = idx >> 6, k = idx & 63;
        W1s[m * 65 + k] = rW1[idx];
    }
    if (threadIdx.x < 32) {
        b1s[threadIdx.x] = rb1[threadIdx.x];
        W2s[threadIdx.x] = rW2[threadIdx.x];
    }
    __syncthreads();
    float b2 = rb2[0];
    int warp = threadIdx.x >> 5, t = threadIdx.x & 31;
    for (int node = blockIdx.x * 8 + warp; node < n; node += gridDim.x * 8) {
        float in0 = hin[node * 64 + t], in1 = hin[node * 64 + t + 32];
        float acc = b1s[t];
#pragma unroll
        for (int k = 0; k < 32; k++) {
            float xk = __shfl_sync(0xffffffffu, in0, k);
            acc += xk * W1s[t * 65 + k];
        }
#pragma unroll
        for (int k = 0; k < 32; k++) {
            float xk = __shfl_sync(0xffffffffu, in1, k);
            acc += xk * W1s[t * 65 + 32 + k];
        }
        acc = fmaxf(acc, 0.f);
        float p = acc * W2s[t];
#pragma unroll
        for (int off = 16; off; off >>= 1) p += __shfl_xor_sync(0xffffffffu, p, off);
        if (t == 0) out[node] = 1.f / (1.f + __expf(-(p + b2)));
    }
}

// ---------------- launch ----------------
extern "C" void kernel_launch(void* const* d_in, const int* in_sizes, int n_in,
                              void* d_out, int out_size) {
    const float* x    = (const float*)d_in[0];
    const int*   ei   = (const int*)d_in[1];
    const float* embW = (const float*)d_in[2];
    const float* embB = (const float*)d_in[3];
    const float* e8W  = (const float*)d_in[4];
    const float* gatW = (const float*)d_in[5];
    const float* attS = (const float*)d_in[6];
    const float* attD = (const float*)d_in[7];
    const float* gatB = (const float*)d_in[8];
    const float* fusW = (const float*)d_in[9];
    const float* fusB = (const float*)d_in[10];
    const float* lnG  = (const float*)d_in[11];
    const float* lnB  = (const float*)d_in[12];
    const float* rW1  = (const float*)d_in[13];
    const float* rb1  = (const float*)d_in[14];
    const float* rW2  = (const float*)d_in[15];
    const float* rb2  = (const float*)d_in[16];
    float* out = (float*)d_out;

    int n = in_sizes[0] / 64;
    int E = in_sizes[1] / 2;
    int n2 = 2 * n;
    int ngrid = 1563;

    // launches 1-4: CSR build
    zero_cnt_kernel<<<(n2 + 255) / 256, 256>>>(n2);
    count_kernel<<<(E + 255) / 256, 256>>>(ei, E, n);
    alloc_kernel<<<(n2 + 255) / 256, 256>>>(n2);
    fill_kernel<<<(E + 255) / 256, 256>>>(ei, E, n);
    // launch 5: dinv + Wc + emb + n1(layer 0)
    nodeprep_kernel<<<ngrid + 48, 256>>>(x, embW, embB, gatW, attS, attD, fusW, e8W, ngrid, n);
    // launch 6: layer 0  <-- ncu -s 5 -c 1 captures this one
    layer_kernel<<<ngrid, 256>>>(fusW, fusB, gatB, lnG, lnB, 0, 0, n);
    for (int l = 1; l < 3; l++) {
        int flip = l & 1;
        n1_kernel<<<ngrid, 256>>>(gatW, attS, attD, l, flip, n);
        layer_kernel<<<ngrid, 256>>>(fusW, fusB, gatB, lnG, lnB, l, flip, n);
    }
    readout_kernel<<<ngrid, 256>>>(rW1, rb1, rW2, rb2, out, n);
}